// round 1
// baseline (speedup 1.0000x reference)
#include <cuda_runtime.h>
#include <cstdint>
#include <math.h>

#define N_SAMP 4096
#define D      128
#define NLAY   5
#define NCU    23          // used Taylor coefficients per neuron
#define NCP    24          // padded
#define SPC    8           // samples per CTA (main)
#define ROWS   (SPC*NCP)   // 192
#define SSTR   132         // shared row stride (floats)
#define NTHR   256
#define RT     12          // rows per thread
#define CT     8           // cols per thread

#define SB     64          // samples per CTA (boundary)
#define BSTR   132

#define TWO_PI 6.2831853071795864769f
#define PI_F   3.1415926535897932385f
#define C2     19.739208802178717238f     /* 2*pi^2  */
#define C3     124.02510672119926149f     /* 4*pi^3  */
#define S_CONST 8.3666002653407556e-04f   /* sqrt(0.7/1e6)   */
#define KAPPA   1.1952286093343936e-03f   /* sqrt(1/7e5)     */

// ---------------- scratch (device globals; no allocation) ----------------
__device__ float g_xy[2*N_SAMP];
__device__ float g_zb[N_SAMP];
__device__ float g_part[(N_SAMP/SPC)*4];   // per-CTA: data, conti, nse, ee
__device__ float g_tbpart[N_SAMP/SB];

// ---------------- threefry2x32-20 (exact JAX) ----------------
__device__ __forceinline__ void tf2(uint32_t k0, uint32_t k1,
                                    uint32_t x0, uint32_t x1,
                                    uint32_t& o0, uint32_t& o1) {
    uint32_t ks2 = k0 ^ k1 ^ 0x1BD11BDAu;
    x0 += k0; x1 += k1;
#define TF_R(r) { x0 += x1; x1 = (x1 << (r)) | (x1 >> (32-(r))); x1 ^= x0; }
    TF_R(13) TF_R(15) TF_R(26) TF_R(6)
    x0 += k1;  x1 += ks2 + 1u;
    TF_R(17) TF_R(29) TF_R(16) TF_R(24)
    x0 += ks2; x1 += k0 + 2u;
    TF_R(13) TF_R(15) TF_R(26) TF_R(6)
    x0 += k0;  x1 += k1 + 3u;
    TF_R(17) TF_R(29) TF_R(16) TF_R(24)
    x0 += k1;  x1 += ks2 + 4u;
    TF_R(13) TF_R(15) TF_R(26) TF_R(6)
    x0 += ks2; x1 += k0 + 5u;
#undef TF_R
    o0 = x0; o1 = x1;
}

__device__ __forceinline__ float u01(uint32_t bits) {
    return __uint_as_float((bits >> 9) | 0x3F800000u) - 1.0f;
}

__global__ void pinn_rng() {
    int i = blockIdx.x * blockDim.x + threadIdx.x;     // 0..4095
    uint32_t a0, a1, b0, b1;
    tf2(0u, 22u, 0u, 2u, a0, a1);   // split(key(22)) lane 0
    tf2(0u, 22u, 1u, 3u, b0, b1);   // lane 1
    // kb1 = (a0,b0), kb2 = (a1,b1)
    uint32_t o0, o1;
    tf2(a0, b0, (uint32_t)i, (uint32_t)(i + 4096), o0, o1);
    g_xy[i]        = u01(o0);
    g_xy[i + 4096] = u01(o1);
    if (i < 2048) {
        uint32_t r0, r1;
        tf2(a1, b1, (uint32_t)i, (uint32_t)(i + 2048), r0, r1);
        g_zb[i]        = (float)(r0 & 1u);
        g_zb[i + 2048] = (float)(r1 & 1u);
    }
}

// ---------------- activation jet propagation ----------------
// coeffs: 0=val, 1..4 = d/dx_i (i=0..3),
// 5..13 second derivs: (0,1),(0,2),(0,3),(1,1),(1,2),(1,3),(2,2),(2,3),(3,3)
// 14..22 third derivs {a,b,b}: (a,b) = (1,1),(2,1),(3,1),(1,2),(2,2),(3,2),(1,3),(2,3),(3,3)
__device__ __forceinline__ void act_prop(float z[NCU]) {
    const int p2a[9] = {0,0,0,1,1,1,2,2,3};
    const int p2b[9] = {1,2,3,1,2,3,2,3,3};
    const int t3a[9] = {1,2,3,1,2,3,1,2,3};
    const int t3b[9] = {1,1,1,2,2,2,3,3,3};
    const int s2s[4][4] = { {0,0,1,2}, {0,3,4,5}, {1,4,6,7}, {2,5,7,8} }; // slot in d2 ([0][0] unused)

    float sv, cv;
    sincosf(TWO_PI * z[0], &sv, &cv);
    float f0 = 0.5f * sv;
    float f1 = PI_F * cv;
    float f2 = -C2 * sv;
    float f3 = -C3 * cv;

    float d1[4], d2[9], d3[9];
#pragma unroll
    for (int i = 0; i < 4; i++) d1[i] = z[1+i];
#pragma unroll
    for (int p = 0; p < 9; p++) d2[p] = z[5+p];
#pragma unroll
    for (int q = 0; q < 9; q++) d3[q] = z[14+q];

    z[0] = f0;
#pragma unroll
    for (int i = 0; i < 4; i++) z[1+i] = f1 * d1[i];
#pragma unroll
    for (int p = 0; p < 9; p++)
        z[5+p] = f1 * d2[p] + f2 * d1[p2a[p]] * d1[p2b[p]];
#pragma unroll
    for (int q = 0; q < 9; q++) {
        int a = t3a[q], b = t3b[q];
        float zbb = d2[s2s[b][b]];
        float zab = d2[s2s[a][b]];
        z[14+q] = f1 * d3[q]
                + f2 * (d1[a]*zbb + 2.0f*d1[b]*zab)
                + f3 * d1[a]*d1[b]*d1[b];
    }
}

// ---------------- main jet-propagation kernel ----------------
__global__ void __launch_bounds__(NTHR, 1)
pinn_main(const float* __restrict__ inputs, const float* __restrict__ y_true,
          const float* __restrict__ Win, const float* __restrict__ bin,
          const float* __restrict__ Wh,  const float* __restrict__ bh,
          const float* __restrict__ Wo,  const float* __restrict__ bo)
{
    extern __shared__ float sm[];
    float* sS  = sm;                     // ROWS*SSTR
    float* sW  = sm + ROWS*SSTR;         // D*D
    float* sx  = sW + D*D;               // 32 floats
    float* sls = sx + 32;                // 8*4 partial losses
    float* yc  = sW;                     // reuse after GEMMs (8*23*4 floats)

    int tid = threadIdx.x;
    int blk = blockIdx.x;
    int s0  = blk * SPC;

    if (tid < SPC*4) sx[tid] = inputs[s0*4 + tid];
    __syncthreads();

    // ---- layer 0: x @ W_in + b_in, init jet, activate ----
    for (int p = tid; p < SPC*D; p += NTHR) {
        int s = p >> 7, n = p & 127;
        float z[NCU];
        float zv = bin[n];
#pragma unroll
        for (int k = 0; k < 4; k++) zv += sx[s*4+k] * Win[k*D+n];
        z[0] = zv;
#pragma unroll
        for (int i = 0; i < 4; i++) z[1+i] = Win[i*D+n];
#pragma unroll
        for (int c = 5; c < NCU; c++) z[c] = 0.0f;
        act_prop(z);
        int rb = (s*NCP)*SSTR + n;
#pragma unroll
        for (int c = 0; c < NCU; c++) sS[rb + c*SSTR] = z[c];
        sS[rb + 23*SSTR] = 0.0f;   // pad row
    }

    int ry = tid >> 4, cx = tid & 15;
    int row0 = ry * RT, col0 = cx * CT;

    // ---- 5 hidden layers ----
    for (int l = 0; l < NLAY; l++) {
        __syncthreads();
        { // load weights
            const float4* Wg = (const float4*)(Wh + l*D*D);
            float4* sW4 = (float4*)sW;
            for (int i = tid; i < D*D/4; i += NTHR) sW4[i] = Wg[i];
        }
        __syncthreads();

        float acc[RT][CT];
#pragma unroll
        for (int i = 0; i < RT; i++)
#pragma unroll
            for (int j = 0; j < CT; j++) acc[i][j] = 0.0f;

        for (int k = 0; k < D; k += 4) {
            float a[RT][4];
#pragma unroll
            for (int i = 0; i < RT; i++) {
                float4 t = *(const float4*)&sS[(row0+i)*SSTR + k];
                a[i][0]=t.x; a[i][1]=t.y; a[i][2]=t.z; a[i][3]=t.w;
            }
#pragma unroll
            for (int kk = 0; kk < 4; kk++) {
                float b[CT];
                float4 t0 = *(const float4*)&sW[(k+kk)*D + col0];
                float4 t1 = *(const float4*)&sW[(k+kk)*D + col0 + 4];
                b[0]=t0.x; b[1]=t0.y; b[2]=t0.z; b[3]=t0.w;
                b[4]=t1.x; b[5]=t1.y; b[6]=t1.z; b[7]=t1.w;
#pragma unroll
                for (int i = 0; i < RT; i++)
#pragma unroll
                    for (int j = 0; j < CT; j++)
                        acc[i][j] += a[i][kk] * b[j];
            }
        }
        __syncthreads();   // all GEMM reads of sS done
#pragma unroll
        for (int i = 0; i < RT; i++)
#pragma unroll
            for (int j = 0; j < CT; j++)
                sS[(row0+i)*SSTR + col0 + j] = acc[i][j];
        __syncthreads();

        // activation (adds bias to value coeff)
        for (int p = tid; p < SPC*D; p += NTHR) {
            int s = p >> 7, n = p & 127;
            float z[NCU];
            int rb = (s*NCP)*SSTR + n;
#pragma unroll
            for (int c = 0; c < NCU; c++) z[c] = sS[rb + c*SSTR];
            z[0] += bh[l*D + n];
            act_prop(z);
#pragma unroll
            for (int c = 0; c < NCU; c++) sS[rb + c*SSTR] = z[c];
        }
    }
    __syncthreads();

    // ---- output layer: yc[s][c][o] = h[s][c][:] . Wo[:,o] (+bias on value) ----
    for (int p = tid; p < SPC*NCU*4; p += NTHR) {
        int s = p / (NCU*4);
        int r = p % (NCU*4);
        int c = r >> 2, o = r & 3;
        float sum = (c == 0) ? bo[o] : 0.0f;
        const float* hr = &sS[(s*NCP + c)*SSTR];
        for (int n = 0; n < D; n++) sum += hr[n] * Wo[n*4 + o];
        yc[(s*NCU + c)*4 + o] = sum;
    }
    __syncthreads();

    // ---- per-sample losses ----
    if (tid < SPC) {
        const int s = tid;
        const int s2c[4][4] = { {0,5,6,7}, {5,8,9,10}, {6,9,11,12}, {7,10,12,13} };
        auto YC = [&](int c, int o) { return yc[(s*NCU + c)*4 + o]; };
        auto Hc = [&](int o, int i, int j) { return YC(s2c[i][j], o); };
        auto Gc = [&](int o, int a, int b) { return YC(14 + (b-1)*3 + (a-1), o); };
        auto J  = [&](int o, int i) { return YC(1+i, o); };

        float u = YC(0,0), v = YC(0,1), w = YC(0,2);
        float u_x=J(0,1), u_y=J(0,2), u_z=J(0,3);
        float v_x=J(1,1), v_y=J(1,2), v_z=J(1,3);
        float w_x=J(2,1), w_y=J(2,2), w_z=J(2,3);
        float T_t=J(3,0), T_x=J(3,1), T_y=J(3,2), T_z=J(3,3);

        float om_x = w_y - v_z, om_y = u_z - w_x, om_z = v_x - u_y;

        float NSE_u = Hc(2,2,0) - Hc(1,3,0)
                    + u*(Hc(2,2,1)-Hc(1,3,1)) + v*(Hc(2,2,2)-Hc(1,3,2)) + w*(Hc(2,2,3)-Hc(1,3,3))
                    - om_x*u_x - om_y*u_y - om_z*u_z
                    - S_CONST*( Gc(2,2,1)-Gc(1,3,1) + Gc(2,2,2)-Gc(1,3,2) + Gc(2,2,3)-Gc(1,3,3) )
                    - T_y;
        float NSE_v = Hc(0,3,0) - Hc(2,1,0)
                    + u*(Hc(0,3,1)-Hc(2,1,1)) + v*(Hc(0,3,2)-Hc(2,1,2)) + w*(Hc(0,3,3)-Hc(2,1,3))
                    - om_x*v_x - om_y*v_y - om_z*v_z
                    - S_CONST*( Gc(0,3,1)-Gc(2,1,1) + Gc(0,3,2)-Gc(2,1,2) + Gc(0,3,3)-Gc(2,1,3) )
                    + T_x;
        float NSE_w = Hc(1,1,0) - Hc(0,2,0)
                    + u*(Hc(1,1,1)-Hc(0,2,1)) + v*(Hc(1,1,2)-Hc(0,2,2)) + w*(Hc(1,1,3)-Hc(0,2,3))
                    - om_x*w_x - om_y*w_y - om_z*w_z
                    - S_CONST*( Gc(1,1,1)-Gc(0,2,1) + Gc(1,1,2)-Gc(0,2,2) + Gc(1,1,3)-Gc(0,2,3) );
        float EE = T_t + u*T_x + v*T_y + w*T_z
                 - KAPPA*( Hc(3,1,1) + Hc(3,2,2) + Hc(3,3,3) );

        float ld = 0.0f;
#pragma unroll
        for (int o = 0; o < 3; o++) {
            float d = YC(0,o) - y_true[(s0+s)*4 + o];
            ld += d*d;
        }
        float conti = u_x + v_y + w_z;
        sls[s*4+0] = ld;
        sls[s*4+1] = conti*conti;
        sls[s*4+2] = NSE_u*NSE_u + NSE_v*NSE_v + NSE_w*NSE_w;
        sls[s*4+3] = EE*EE;
    }
    __syncthreads();
    if (tid == 0) {
        float a0=0, a1=0, a2=0, a3=0;
        for (int s = 0; s < SPC; s++) {
            a0 += sls[s*4+0]; a1 += sls[s*4+1];
            a2 += sls[s*4+2]; a3 += sls[s*4+3];
        }
        g_part[blk*4+0] = a0; g_part[blk*4+1] = a1;
        g_part[blk*4+2] = a2; g_part[blk*4+3] = a3;
    }
}

// ---------------- boundary batch (value-only propagation) ----------------
__global__ void __launch_bounds__(256, 1)
pinn_bound(const float* __restrict__ inputs,
           const float* __restrict__ Win, const float* __restrict__ bin,
           const float* __restrict__ Wh,  const float* __restrict__ bh,
           const float* __restrict__ Wo,  const float* __restrict__ bo)
{
    extern __shared__ float sm[];
    float* sH  = sm;                // SB*BSTR
    float* sW  = sm + SB*BSTR;      // D*D
    float* red = sW + D*D;          // 256

    int tid = threadIdx.x;
    int blk = blockIdx.x;
    int s0 = blk * SB;

    for (int p = tid; p < SB*D; p += 256) {
        int s = p >> 7, n = p & 127;
        int gs = s0 + s;
        float t  = inputs[gs*4];
        float xb = g_xy[2*gs], yb = g_xy[2*gs+1], zb = g_zb[gs];
        float z = bin[n] + t*Win[n] + xb*Win[D+n] + yb*Win[2*D+n] + zb*Win[3*D+n];
        sH[s*BSTR + n] = 0.5f * sinf(TWO_PI * z);
    }

    int ry = tid >> 4, cx = tid & 15;
    int row0 = ry * 4, col0 = cx * 8;

    for (int l = 0; l < NLAY; l++) {
        __syncthreads();
        {
            const float4* Wg = (const float4*)(Wh + l*D*D);
            float4* sW4 = (float4*)sW;
            for (int i = tid; i < D*D/4; i += 256) sW4[i] = Wg[i];
        }
        __syncthreads();

        float acc[4][8];
#pragma unroll
        for (int i = 0; i < 4; i++)
#pragma unroll
            for (int j = 0; j < 8; j++) acc[i][j] = 0.0f;

        for (int k = 0; k < D; k += 4) {
            float a[4][4];
#pragma unroll
            for (int i = 0; i < 4; i++) {
                float4 t = *(const float4*)&sH[(row0+i)*BSTR + k];
                a[i][0]=t.x; a[i][1]=t.y; a[i][2]=t.z; a[i][3]=t.w;
            }
#pragma unroll
            for (int kk = 0; kk < 4; kk++) {
                float b[8];
                float4 t0 = *(const float4*)&sW[(k+kk)*D + col0];
                float4 t1 = *(const float4*)&sW[(k+kk)*D + col0 + 4];
                b[0]=t0.x; b[1]=t0.y; b[2]=t0.z; b[3]=t0.w;
                b[4]=t1.x; b[5]=t1.y; b[6]=t1.z; b[7]=t1.w;
#pragma unroll
                for (int i = 0; i < 4; i++)
#pragma unroll
                    for (int j = 0; j < 8; j++)
                        acc[i][j] += a[i][kk] * b[j];
            }
        }
        __syncthreads();
#pragma unroll
        for (int i = 0; i < 4; i++)
#pragma unroll
            for (int j = 0; j < 8; j++)
                sH[(row0+i)*BSTR + col0 + j] = acc[i][j];
        __syncthreads();
        for (int p = tid; p < SB*D; p += 256) {
            int s = p >> 7, n = p & 127;
            float z = sH[s*BSTR + n] + bh[l*D + n];
            sH[s*BSTR + n] = 0.5f * sinf(TWO_PI * z);
        }
    }
    __syncthreads();

    {   // T = h . Wo[:,3] + bo[3]
        int s = tid & 63, q = tid >> 6;
        float part = 0.0f;
        for (int n = q*32; n < q*32 + 32; n++)
            part += sH[s*BSTR + n] * Wo[n*4 + 3];
        red[tid] = part;
    }
    __syncthreads();
    if (tid < 64) {
        float T = red[tid] + red[tid+64] + red[tid+128] + red[tid+192] + bo[3];
        float Tt = (g_zb[s0 + tid] == 0.0f) ? 0.5f : -0.5f;
        float d = Tt - T;
        red[tid] = d * d;
    }
    __syncthreads();
    if (tid == 0) {
        float a = 0.0f;
        for (int i = 0; i < 64; i++) a += red[i];
        g_tbpart[blk] = a;
    }
}

// ---------------- final reduction ----------------
__global__ void pinn_reduce(float* __restrict__ out) {
    __shared__ double sd[512];
    int tid = threadIdx.x;   // 512 threads

    double pv[4] = {0.0, 0.0, 0.0, 0.0};
    if (tid < N_SAMP/SPC) {
        pv[0] = (double)g_part[tid*4+0];
        pv[1] = (double)g_part[tid*4+1];
        pv[2] = (double)g_part[tid*4+2];
        pv[3] = (double)g_part[tid*4+3];
    }
    double tb = (tid < N_SAMP/SB) ? (double)g_tbpart[tid] : 0.0;

    double sums[5];
    double vals[5] = {pv[0], pv[1], pv[2], pv[3], tb};
    for (int q = 0; q < 5; q++) {
        sd[tid] = vals[q];
        __syncthreads();
        for (int o = 256; o > 0; o >>= 1) {
            if (tid < o) sd[tid] += sd[tid + o];
            __syncthreads();
        }
        sums[q] = sd[0];
        __syncthreads();
    }
    if (tid == 0) {
        double Nf = (double)N_SAMP;
        double total = sums[0]/(3.0*Nf)   // data
                     + sums[1]/Nf         // conti
                     + sums[2]/(3.0*Nf)   // NSE
                     + sums[3]/Nf         // EE
                     + sums[4]/Nf;        // Tb
        out[0] = (float)total;
    }
}

// ---------------- launch ----------------
extern "C" void kernel_launch(void* const* d_in, const int* in_sizes, int n_in,
                              void* d_out, int out_size) {
    const float* inputs = (const float*)d_in[0];
    const float* y_true = (const float*)d_in[1];
    const float* Win    = (const float*)d_in[2];
    const float* bin    = (const float*)d_in[3];
    const float* Wh     = (const float*)d_in[4];
    const float* bh     = (const float*)d_in[5];
    const float* Wo     = (const float*)d_in[6];
    const float* bo     = (const float*)d_in[7];
    float* out = (float*)d_out;

    size_t shm_main = (size_t)(ROWS*SSTR + D*D + 32 + 32) * sizeof(float);
    size_t shm_b    = (size_t)(SB*BSTR + D*D + 256) * sizeof(float);
    cudaFuncSetAttribute(pinn_main,  cudaFuncAttributeMaxDynamicSharedMemorySize, (int)shm_main);
    cudaFuncSetAttribute(pinn_bound, cudaFuncAttributeMaxDynamicSharedMemorySize, (int)shm_b);

    pinn_rng<<<16, 256>>>();
    pinn_main<<<N_SAMP/SPC, NTHR, shm_main>>>(inputs, y_true, Win, bin, Wh, bh, Wo, bo);
    pinn_bound<<<N_SAMP/SB, 256, shm_b>>>(inputs, Win, bin, Wh, bh, Wo, bo);
    pinn_reduce<<<1, 512>>>(out);
}